// round 3
// baseline (speedup 1.0000x reference)
#include <cuda_runtime.h>

// OWA pooling: 3x3 window, stride 2, SAME pad (0 top/left, 1 bottom/right),
// sort window descending, dot with per-channel rank weights.
// inputs: (16,224,224,64) f32 NHWC ; kernel: (9,64) f32 ; out: (16,112,112,64) f32

#define B_  16
#define H_  224
#define W_  224
#define C_  64
#define OH_ 112
#define OW_ 112
#define OW_PER_WARP 14   // 112 / 8 warps

// Zero pad row: row-2 base pointer is redirected here for the bottom-pad case.
// Device globals are zero-initialized and never written.
__device__ float ZROW[(W_ + 8) * C_];

// Descending compare-exchange on float2 (two independent channels)
#define CE(i, j)                                          \
    {                                                     \
        float tx = fmaxf(w[i].x, w[j].x);                 \
        float ty = fmaxf(w[i].y, w[j].y);                 \
        w[j].x = fminf(w[i].x, w[j].x);                   \
        w[j].y = fminf(w[i].y, w[j].y);                   \
        w[i].x = tx;                                      \
        w[i].y = ty;                                      \
    }

__global__ __launch_bounds__(256, 4) void owa_pool_kernel(
    const float* __restrict__ in,   // (B,H,W,C)
    const float* __restrict__ kw,   // (9,C)
    float* __restrict__ out)        // (B,OH,OW,C)
{
    const int oh   = blockIdx.x;
    const int b    = blockIdx.y;
    const int warp = threadIdx.x >> 5;
    const int lane = threadIdx.x & 31;
    const int c    = lane * 2;          // this thread's channel pair

    // Per-rank weights for this channel pair (9 float2, loop-invariant)
    float2 wgt[9];
#pragma unroll
    for (int k = 0; k < 9; k++)
        wgt[k] = *reinterpret_cast<const float2*>(kw + k * C_ + c);

    const int r0 = oh * 2;
    const float* base0 = in + ((b * H_ + r0) * W_) * C_ + c;
    const float* base1 = base0 + W_ * C_;
    // Bottom pad: when oh == 111, row r0+2 doesn't exist -> read zeros.
    const float* base2 = (r0 + 2 < H_) ? (base0 + 2 * W_ * C_) : (ZROW + c);

    // Load one input column (3 rows) of this channel pair; zeros for right pad.
    auto loadcol = [&](int col, float2* dst) {
        if (col < W_) {
            dst[0] = *reinterpret_cast<const float2*>(base0 + col * C_);
            dst[1] = *reinterpret_cast<const float2*>(base1 + col * C_);
            dst[2] = *reinterpret_cast<const float2*>(base2 + col * C_);
        } else {
            dst[0] = make_float2(0.f, 0.f);
            dst[1] = make_float2(0.f, 0.f);
            dst[2] = make_float2(0.f, 0.f);
        }
    };

    const int ow0 = warp * OW_PER_WARP;

    // Window registers: w[0..2]=col 2ow, w[3..5]=col 2ow+1, w[6..8]=col 2ow+2
    float2 w[9];
    loadcol(2 * ow0,     &w[0]);
    loadcol(2 * ow0 + 1, &w[3]);
    loadcol(2 * ow0 + 2, &w[6]);

    float* orow = out + ((b * OH_ + oh) * OW_) * C_ + c;

#pragma unroll 1
    for (int ow = ow0; ow < ow0 + OW_PER_WARP; ++ow) {
        // Prefetch next iteration's two fresh columns NOW; the 25-CE sort
        // below hides their (L2/DRAM) latency within this warp.
        float2 n1[3], n2[3];
        loadcol(2 * ow + 3, n1);
        loadcol(2 * ow + 4, n2);

        // Optimal 9-input sorting network: 25 CEs, depth 7 (descending),
        // sorting the window IN PLACE (no copy -> fewer live registers).
        CE(0,3) CE(1,7) CE(2,5) CE(4,8)
        CE(0,7) CE(2,4) CE(3,8) CE(5,6)
        CE(0,2) CE(1,3) CE(4,5) CE(7,8)
        CE(1,4) CE(3,6) CE(5,7)
        CE(0,1) CE(2,4) CE(3,5) CE(6,8)
        CE(2,3) CE(4,5) CE(6,7)
        CE(1,2) CE(3,4) CE(5,6)

        // Rank-weighted sum (w[0] is the max, matching -sort(-p))
        float accx = w[0].x * wgt[0].x;
        float accy = w[0].y * wgt[0].y;
#pragma unroll
        for (int k = 1; k < 9; k++) {
            accx = fmaf(w[k].x, wgt[k].x, accx);
            accy = fmaf(w[k].y, wgt[k].y, accy);
        }

        // Re-load the shared boundary column (read last by this warp one
        // iteration ago -> L1 hit) instead of carrying it in registers.
        loadcol(2 * ow + 2, &w[0]);
        w[3] = n1[0]; w[4] = n1[1]; w[5] = n1[2];
        w[6] = n2[0]; w[7] = n2[1]; w[8] = n2[2];

        // Streaming store: output is write-once, keep L2 for shared input rows.
        __stcs(reinterpret_cast<float2*>(orow + ow * C_),
               make_float2(accx, accy));
    }
}

extern "C" void kernel_launch(void* const* d_in, const int* in_sizes, int n_in,
                              void* d_out, int out_size)
{
    const float* in = (const float*)d_in[0];   // (16,224,224,64)
    const float* kw = (const float*)d_in[1];   // (9,64)
    float* out = (float*)d_out;                // (16,112,112,64)

    dim3 grid(OH_, B_);
    dim3 block(256);
    owa_pool_kernel<<<grid, block>>>(in, kw, out);
}

// round 4
// speedup vs baseline: 1.2102x; 1.2102x over previous
#include <cuda_runtime.h>

// OWA pooling: 3x3 window, stride 2, SAME pad (0 top/left, 1 bottom/right),
// sort window descending, dot with per-channel rank weights.
// inputs: (16,224,224,64) f32 NHWC ; kernel: (9,64) f32 ; out: (16,112,112,64) f32

#define B_  16
#define H_  224
#define W_  224
#define C_  64
#define OH_ 112
#define OW_ 112
#define OW_PER_WARP 14   // 112 / 8 warps

// Descending compare-exchange, FMNMX form (alu pipe): 4 ops per float2
#define CE(i, j)                                          \
    {                                                     \
        float tx = fmaxf(v[i].x, v[j].x);                 \
        float ty = fmaxf(v[i].y, v[j].y);                 \
        v[j].x = fminf(v[i].x, v[j].x);                   \
        v[j].y = fminf(v[i].y, v[j].y);                   \
        v[i].x = tx;                                      \
        v[i].y = ty;                                      \
    }

// Descending compare-exchange, arithmetic form (fma pipe):
// max = 0.5*((a+b)+|a-b|), min = 0.5*((a+b)-|a-b|).
// FADD/FMUL only -> runs on the fma pipe, balancing against FMNMX on alu.
#define CEF(i, j)                                         \
    {                                                     \
        float sx = v[i].x + v[j].x;                       \
        float dx = v[i].x - v[j].x;                       \
        float sy = v[i].y + v[j].y;                       \
        float dy = v[i].y - v[j].y;                       \
        float mxx = sx + fabsf(dx);                       \
        float mnx = sx - fabsf(dx);                       \
        float mxy = sy + fabsf(dy);                       \
        float mny = sy - fabsf(dy);                       \
        v[i].x = 0.5f * mxx;                              \
        v[j].x = 0.5f * mnx;                              \
        v[i].y = 0.5f * mxy;                              \
        v[j].y = 0.5f * mny;                              \
    }

__global__ __launch_bounds__(256, 3) void owa_pool_kernel(
    const float* __restrict__ in,   // (B,H,W,C)
    const float* __restrict__ kw,   // (9,C)
    float* __restrict__ out)        // (B,OH,OW,C)
{
    const int oh   = blockIdx.x;
    const int b    = blockIdx.y;
    const int warp = threadIdx.x >> 5;
    const int lane = threadIdx.x & 31;
    const int c    = lane * 2;          // this thread's channel pair

    // Per-rank weights for this channel pair (loop-invariant)
    float2 wgt[9];
#pragma unroll
    for (int k = 0; k < 9; k++)
        wgt[k] = *reinterpret_cast<const float2*>(kw + k * C_ + c);

    const int r0 = oh * 2;
    const bool r2ok = (r0 + 2 < H_);    // bottom pad row when oh == 111
    const float* base = in + ((b * H_ + r0) * W_) * C_ + c;

    // Load one input column (3 rows) of this channel pair; zeros for pad.
    auto loadcol = [&](int col, float2* dst) {
        if (col < W_) {
            dst[0] = *reinterpret_cast<const float2*>(base + col * C_);
            dst[1] = *reinterpret_cast<const float2*>(base + (W_ + col) * C_);
            dst[2] = r2ok
                   ? *reinterpret_cast<const float2*>(base + (2 * W_ + col) * C_)
                   : make_float2(0.f, 0.f);
        } else {                        // right pad column
            dst[0] = make_float2(0.f, 0.f);
            dst[1] = make_float2(0.f, 0.f);
            dst[2] = make_float2(0.f, 0.f);
        }
    };

    const int ow0 = warp * OW_PER_WARP;

    float2 c0[3], c1[3], c2[3];
    loadcol(2 * ow0,     c0);
    loadcol(2 * ow0 + 1, c1);
    loadcol(2 * ow0 + 2, c2);

    float* orow = out + ((b * OH_ + oh) * OW_) * C_ + c;

    // Fully unrolled: rotation/gather copies become register renames,
    // loop overhead disappears, ptxas schedules loads globally.
#pragma unroll
    for (int i = 0; i < OW_PER_WARP; ++i) {
        const int ow = ow0 + i;

        // Gather window into sort workspace (renamed away after unroll)
        float2 v[9];
        v[0] = c0[0]; v[1] = c0[1]; v[2] = c0[2];
        v[3] = c1[0]; v[4] = c1[1]; v[5] = c1[2];
        v[6] = c2[0]; v[7] = c2[1]; v[8] = c2[2];

        // Rotate and issue next columns' loads so the sort hides latency.
        c0[0] = c2[0]; c0[1] = c2[1]; c0[2] = c2[2];
        if (i + 1 < OW_PER_WARP) {
            loadcol(2 * ow + 3, c1);
            loadcol(2 * ow + 4, c2);
        }

        // Optimal 9-input sorting network: 25 CEs, depth 7 (descending).
        // 5 CEs routed to the fma pipe (CEF) to balance pipe load.
        CEF(0,3) CEF(1,7) CEF(2,5) CEF(4,8)
        CE(0,7) CE(2,4) CE(3,8) CEF(5,6)
        CE(0,2) CE(1,3) CE(4,5) CE(7,8)
        CE(1,4) CE(3,6) CE(5,7)
        CE(0,1) CE(2,4) CE(3,5) CE(6,8)
        CE(2,3) CE(4,5) CE(6,7)
        CE(1,2) CE(3,4) CE(5,6)

        // Rank-weighted sum (v[0] is the max, matching -sort(-p))
        float accx = v[0].x * wgt[0].x;
        float accy = v[0].y * wgt[0].y;
#pragma unroll
        for (int k = 1; k < 9; k++) {
            accx = fmaf(v[k].x, wgt[k].x, accx);
            accy = fmaf(v[k].y, wgt[k].y, accy);
        }

        *reinterpret_cast<float2*>(orow + ow * C_) = make_float2(accx, accy);
    }
}

extern "C" void kernel_launch(void* const* d_in, const int* in_sizes, int n_in,
                              void* d_out, int out_size)
{
    const float* in = (const float*)d_in[0];   // (16,224,224,64)
    const float* kw = (const float*)d_in[1];   // (9,64)
    float* out = (float*)d_out;                // (16,112,112,64)

    dim3 grid(OH_, B_);
    dim3 block(256);
    owa_pool_kernel<<<grid, block>>>(in, kw, out);
}